// round 7
// baseline (speedup 1.0000x reference)
#include <cuda_runtime.h>
#include <math.h>

#define S_LEN 128
#define BATCH 64
#define EMB   256
#define HID_H 256
#define NHID  30

typedef unsigned long long ull;

// ---------------- f32x2 helpers (FFMA2 only reachable via PTX) ----------------
__device__ __forceinline__ ull fma2(ull a, ull b, ull c) {
    ull d;
    asm("fma.rn.f32x2 %0, %1, %2, %3;" : "=l"(d) : "l"(a), "l"(b), "l"(c));
    return d;
}
__device__ __forceinline__ ull pack2(float lo, float hi) {
    ull d;
    asm("mov.b64 %0, {%1, %2};" : "=l"(d) : "f"(lo), "f"(hi));
    return d;
}
__device__ __forceinline__ void unpack2(ull v, float& lo, float& hi) {
    asm("mov.b64 {%0, %1}, %2;" : "=f"(lo), "=f"(hi) : "l"(v));
}

// ---------------- scratch (device globals; no allocation allowed) ----------------
// pre-gates: ((t*2+dir)*1024 + row)*64 + b   (includes bias)
__device__ float g_X[S_LEN * 2 * 1024 * BATCH];                 // 64 MB
// h ping-pong: (((par*2+dir)*2+bhalf)*256 + k)*32 + b32
__device__ float g_h[2 * 2 * 2 * 256 * 32];                     // 256 KB
// enc: (b*128 + t)*512 + c   (c<256 fwd, c>=256 bwd), valid-masked
__device__ float g_enc[BATCH * S_LEN * 512];                    // 16.8 MB
// u/w packed: (pos)*64 + c   (c<30: u, 32<=c<62: w), pos = b*128+t
__device__ float g_uw[BATCH * S_LEN * 64];                      // 2 MB
// grid barrier: [grp 0..3][step 0..128]
__device__ int g_bar2[4 * 129];

// ---------------- barrier reset ----------------
__global__ void zerobar_kernel() {
    for (int i = threadIdx.x; i < 4 * 129; i += blockDim.x) g_bar2[i] = 0;
}

// ---------------- stage 1: pre-gates GEMM, f32x2, fused embedding gather ----------------
// grid (16 rowtiles, 128 t), block 256. Tile: 128 rows x 64 batches, k-block 16.
// A2: [k][m] broadcast pairs {w,w} (ull, row stride 130 -> conflict-free STS/LDS)
// B2: [k][bp] batch pairs {emb[2bp], emb[2bp+1]}
__global__ void __launch_bounds__(256) pregemm_kernel(
    const int* __restrict__ concepts, const int* __restrict__ lens,
    const float* __restrict__ embedding,
    const float* __restrict__ Wih_f, const float* __restrict__ b_f,
    const float* __restrict__ Wih_b, const float* __restrict__ b_b)
{
    __shared__ ull A2[16 * 130];
    __shared__ ull B2[16 * 34];
    __shared__ int tok_s[64];

    int t = blockIdx.y;
    int rowbase = blockIdx.x * 128;
    int dir = rowbase >> 10;
    int row0 = rowbase & 1023;
    const float* W    = dir ? Wih_b : Wih_f;
    const float* bias = dir ? b_b   : b_f;
    int tid = threadIdx.x;

    if (tid < 64) {
        int b = tid;
        int srow = t;
        if (dir) { int L = lens[b]; srow = (t < L) ? (L - 1 - t) : t; }
        tok_s[b] = concepts[srow * 64 + b];
    }
    __syncthreads();

    int tx = tid & 15, ty = tid >> 4;   // tx: 4 batches, ty: 8 rows
    ull acc[8][2];
    #pragma unroll
    for (int i = 0; i < 8; i++) { acc[i][0] = 0ull; acc[i][1] = 0ull; }

    for (int k0 = 0; k0 < 256; k0 += 16) {
        // A fill: 512 float4 (128 m x 4 k-quads), 2 per thread
        #pragma unroll
        for (int i = 0; i < 2; i++) {
            int fidx = i * 256 + tid;
            int m = fidx >> 2, q = fidx & 3;
            float4 w4 = *(const float4*)&W[(row0 + m) * 256 + k0 + q * 4];
            A2[(q * 4 + 0) * 130 + m] = pack2(w4.x, w4.x);
            A2[(q * 4 + 1) * 130 + m] = pack2(w4.y, w4.y);
            A2[(q * 4 + 2) * 130 + m] = pack2(w4.z, w4.z);
            A2[(q * 4 + 3) * 130 + m] = pack2(w4.w, w4.w);
        }
        // B fill: 512 pairs (32 bp x 16 k), 2 per thread
        #pragma unroll
        for (int i = 0; i < 2; i++) {
            int fidx = i * 256 + tid;
            int bp = fidx >> 4, k = fidx & 15;
            float v0 = embedding[(long)tok_s[2 * bp]     * 256 + k0 + k];
            float v1 = embedding[(long)tok_s[2 * bp + 1] * 256 + k0 + k];
            B2[k * 34 + bp] = pack2(v0, v1);
        }
        __syncthreads();
        #pragma unroll
        for (int k = 0; k < 16; k++) {
            ulonglong2 bb = *(const ulonglong2*)&B2[k * 34 + tx * 2];
            #pragma unroll
            for (int u = 0; u < 4; u++) {
                ulonglong2 a = *(const ulonglong2*)&A2[k * 130 + ty * 8 + u * 2];
                acc[u * 2    ][0] = fma2(a.x, bb.x, acc[u * 2    ][0]);
                acc[u * 2    ][1] = fma2(a.x, bb.y, acc[u * 2    ][1]);
                acc[u * 2 + 1][0] = fma2(a.y, bb.x, acc[u * 2 + 1][0]);
                acc[u * 2 + 1][1] = fma2(a.y, bb.y, acc[u * 2 + 1][1]);
            }
        }
        __syncthreads();
    }

    #pragma unroll
    for (int i = 0; i < 8; i++) {
        int m = ty * 8 + i;
        float bv = bias[row0 + m];
        float x0, x1, x2, x3;
        unpack2(acc[i][0], x0, x1);
        unpack2(acc[i][1], x2, x3);
        float4 o = make_float4(x0 + bv, x1 + bv, x2 + bv, x3 + bv);
        *(float4*)&g_X[(((long)t * 2 + dir) * 1024 + row0 + m) * 64 + tx * 4] = o;
    }
}

// ---------------- stage 2: persistent LSTM recurrence, f32x2 gate-pairs ----------------
// 128 CTAs: dir=cta>>6, bhalf=(cta&63)>>5, jgrp=cta&31 (8 hidden units).
// smem: wif[8j][256k] {Wi,Wf} pairs, wgo likewise, h2[32b][258k] broadcast pairs {h,h}.
__global__ void __launch_bounds__(256, 1) recur_kernel(
    const float* __restrict__ Whh_f, const float* __restrict__ Whh_b,
    const int* __restrict__ lens)
{
    extern __shared__ ull sm2[];
    ull* wif = sm2;                 // 2048
    ull* wgo = sm2 + 2048;          // 2048
    ull* h2  = sm2 + 4096;          // 32 * 258 = 8256

    int cta = blockIdx.x;
    int dir   = cta >> 6;
    int bhalf = (cta & 63) >> 5;
    int jgrp  = cta & 31;
    int tid = threadIdx.x;
    int j = tid >> 5, lane = tid & 31;
    int hidx = jgrp * 8 + j;
    int bglob = bhalf * 32 + lane;
    int grp = dir * 2 + bhalf;
    const float* Whh = dir ? Whh_b : Whh_f;
    int L = lens[bglob];

    // weight fill: pack gate pairs (i,f) and (g,o)
    #pragma unroll
    for (int i = 0; i < 4; i++) {
        int idx = i * 256 + tid;                 // 1024 = 2 pairsel x 8 j x 64 kq
        int pairsel = idx >> 9;
        int rem = idx & 511;
        int jj = rem >> 6, kq = rem & 63;
        int hrow = jgrp * 8 + jj;
        float4 wa = *(const float4*)&Whh[((pairsel * 2 + 0) * 256 + hrow) * 256 + kq * 4];
        float4 wb = *(const float4*)&Whh[((pairsel * 2 + 1) * 256 + hrow) * 256 + kq * 4];
        ull* dst = (pairsel ? wgo : wif) + jj * 256 + kq * 4;
        dst[0] = pack2(wa.x, wb.x);
        dst[1] = pack2(wa.y, wb.y);
        dst[2] = pack2(wa.z, wb.z);
        dst[3] = pack2(wa.w, wb.w);
    }

    // init: zero parity-1 h slot (t=0 reads parity 1)
    g_h[(((1 * 2 + dir) * 2 + bhalf) * 256 + hidx) * 32 + lane] = 0.f;
    __threadfence();
    __syncthreads();
    if (tid == 0) atomicAdd(&g_bar2[grp * 129 + 0], 1);

    float c = 0.f;
    volatile int* barv = (volatile int*)g_bar2;
    const ull* wifj = wif + j * 256;
    const ull* wgoj = wgo + j * 256;
    const ull* hb = h2 + lane * 258;

    for (int t = 0; t < S_LEN; t++) {
        // X loads before barrier (g_X is static after pregemm)
        long xb = ((long)t * 2 + dir) * 1024 * 64;
        float x0 = g_X[xb + (0   + hidx) * 64 + bglob];
        float x1 = g_X[xb + (256 + hidx) * 64 + bglob];
        float x2 = g_X[xb + (512 + hidx) * 64 + bglob];
        float x3 = g_X[xb + (768 + hidx) * 64 + bglob];
        ull acc01a = pack2(x0, x1), acc01b = 0ull;
        ull acc23a = pack2(x2, x3), acc23b = 0ull;

        if (tid == 0) {
            while (barv[grp * 129 + t] < 32) { __nanosleep(64); }
        }
        __syncthreads();
        __threadfence();

        // stage h_prev: transpose + broadcast-pack into smem
        {
            int rp = (t + 1) & 1;
            const float* hp = &g_h[((rp * 2 + dir) * 2 + bhalf) * 8192];
            #pragma unroll
            for (int i = 0; i < 8; i++) {
                int fidx = i * 256 + tid;        // 2048 float4
                int kk = fidx >> 3, bq = fidx & 7;
                float4 hv = __ldcg((const float4*)(hp + kk * 32 + bq * 4));
                h2[(bq * 4 + 0) * 258 + kk] = pack2(hv.x, hv.x);
                h2[(bq * 4 + 1) * 258 + kk] = pack2(hv.y, hv.y);
                h2[(bq * 4 + 2) * 258 + kk] = pack2(hv.z, hv.z);
                h2[(bq * 4 + 3) * 258 + kk] = pack2(hv.w, hv.w);
            }
        }
        __syncthreads();

        #pragma unroll 8
        for (int k = 0; k < 256; k += 4) {
            ulonglong2 hA = *(const ulonglong2*)&hb[k];
            ulonglong2 hB = *(const ulonglong2*)&hb[k + 2];
            ulonglong2 w0 = *(const ulonglong2*)&wifj[k];
            ulonglong2 w1 = *(const ulonglong2*)&wifj[k + 2];
            ulonglong2 w2 = *(const ulonglong2*)&wgoj[k];
            ulonglong2 w3 = *(const ulonglong2*)&wgoj[k + 2];
            acc01a = fma2(w0.x, hA.x, acc01a);
            acc01b = fma2(w0.y, hA.y, acc01b);
            acc01a = fma2(w1.x, hB.x, acc01a);
            acc01b = fma2(w1.y, hB.y, acc01b);
            acc23a = fma2(w2.x, hA.x, acc23a);
            acc23b = fma2(w2.y, hA.y, acc23b);
            acc23a = fma2(w3.x, hB.x, acc23a);
            acc23b = fma2(w3.y, hB.y, acc23b);
        }

        float ai0, af0, ai1, af1, ag0, ao0, ag1, ao1;
        unpack2(acc01a, ai0, af0);
        unpack2(acc01b, ai1, af1);
        unpack2(acc23a, ag0, ao0);
        unpack2(acc23b, ag1, ao1);
        float a0 = ai0 + ai1, a1 = af0 + af1, a2 = ag0 + ag1, a3 = ao0 + ao1;

        float ig = 1.f / (1.f + expf(-a0));
        float fg = 1.f / (1.f + expf(-a1));
        float gg = tanhf(a2);
        float og = 1.f / (1.f + expf(-a3));
        c = fg * c + ig * gg;
        float hval = og * tanhf(c);

        // fused enc write (valid mask + backward un-reversal)
        bool valid = (t < L);
        float ev = valid ? hval : 0.f;
        if (dir == 0) {
            g_enc[((long)bglob * 128 + t) * 512 + hidx] = ev;
        } else {
            int tp = valid ? (L - 1 - t) : t;
            g_enc[((long)bglob * 128 + tp) * 512 + 256 + hidx] = ev;
        }

        if (t < S_LEN - 1) {
            int wp = t & 1;
            g_h[(((wp * 2 + dir) * 2 + bhalf) * 256 + hidx) * 32 + lane] = hval;
            __threadfence();
            __syncthreads();
            if (tid == 0) atomicAdd(&g_bar2[grp * 129 + t + 1], 1);
        }
    }
}

// ---------------- stage 3: u/w projections (enc[8192,512] @ W2[512,64]) ----------------
// grid 256 (pos tiles of 32), block 256, c-tile full 64 (c<30: Ua, 32..61: Wa)
__global__ void __launch_bounds__(256) uw_kernel(
    const float* __restrict__ Ua, const float* __restrict__ Wa)
{
    __shared__ float A_s[32 * 17];
    __shared__ float B_s[16 * 68];
    int pos0 = blockIdx.x * 32;
    int tid = threadIdx.x;
    int tx = tid & 15, ty = tid >> 4;

    float acc[2][4];
    #pragma unroll
    for (int i = 0; i < 2; i++) { acc[i][0]=0.f; acc[i][1]=0.f; acc[i][2]=0.f; acc[i][3]=0.f; }

    for (int k0 = 0; k0 < 512; k0 += 16) {
        #pragma unroll
        for (int i = 0; i < 2; i++) {
            int idx = i * 256 + tid;
            int m = idx >> 4, k = idx & 15;
            A_s[m * 17 + k] = g_enc[(long)(pos0 + m) * 512 + k0 + k];
        }
        #pragma unroll
        for (int i = 0; i < 4; i++) {
            int idx = i * 256 + tid;
            int kk = idx >> 6, cc = idx & 63;
            float v = 0.f;
            if (cc < 30) v = Ua[cc * 512 + k0 + kk];
            else if (cc >= 32 && cc < 62) v = Wa[(cc - 32) * 512 + k0 + kk];
            B_s[kk * 68 + cc] = v;
        }
        __syncthreads();
        #pragma unroll
        for (int k = 0; k < 16; k++) {
            float4 b4 = *(const float4*)&B_s[k * 68 + tx * 4];
            #pragma unroll
            for (int i = 0; i < 2; i++) {
                float a = A_s[(ty * 2 + i) * 17 + k];
                acc[i][0] = fmaf(a, b4.x, acc[i][0]);
                acc[i][1] = fmaf(a, b4.y, acc[i][1]);
                acc[i][2] = fmaf(a, b4.z, acc[i][2]);
                acc[i][3] = fmaf(a, b4.w, acc[i][3]);
            }
        }
        __syncthreads();
    }
    #pragma unroll
    for (int i = 0; i < 2; i++) {
        *(float4*)&g_uw[(long)(pos0 + ty * 2 + i) * 64 + tx * 4] =
            make_float4(acc[i][0], acc[i][1], acc[i][2], acc[i][3]);
    }
}

// ---------------- stage 4: edge scores + predictions ----------------
// grid (4 qtiles, 64 b), block 256. scores[b][q][k] = sum_h va[h]*tanh(u[b,q,h]+w[b,k,h])
__global__ void __launch_bounds__(256) scores_kernel(
    const float* __restrict__ va, float* __restrict__ out, long out_size)
{
    __shared__ float u_s[32 * 33];
    __shared__ float w_s[128 * 33];
    __shared__ float va_s[30];

    int b = blockIdx.y;
    int q0 = blockIdx.x * 32;
    int tid = threadIdx.x;

    for (int i = tid; i < 128 * 32; i += 256) {
        int k = i >> 5, h = i & 31;
        w_s[k * 33 + h] = g_uw[((long)b * 128 + k) * 64 + 32 + h];
    }
    for (int i = tid; i < 32 * 32; i += 256) {
        int q = i >> 5, h = i & 31;
        u_s[q * 33 + h] = g_uw[((long)b * 128 + q0 + q) * 64 + h];
    }
    if (tid < 30) va_s[tid] = va[tid];
    __syncthreads();

    int kk = tid & 127;
    int qoff = tid >> 7;
    bool preds = (out_size >= 2097152);
    #pragma unroll 1
    for (int i = 0; i < 16; i++) {
        int q = qoff * 16 + i;
        float s = 0.f;
        #pragma unroll
        for (int h = 0; h < 30; h++) {
            s = fmaf(va_s[h], tanhf(u_s[q * 33 + h] + w_s[kk * 33 + h]), s);
        }
        long oidx = ((long)b * 128 + q0 + q) * 128 + kk;
        out[oidx] = s;
        if (preds) out[1048576 + oidx] = (s >= 0.f) ? 1.f : 0.f;
    }
}

// ---------------- launch ----------------
extern "C" void kernel_launch(void* const* d_in, const int* in_sizes, int n_in,
                              void* d_out, int out_size) {
    const int*   concepts  = (const int*)  d_in[0];
    const int*   lens      = (const int*)  d_in[1];
    const float* embedding = (const float*)d_in[2];
    const float* Wih_f     = (const float*)d_in[3];
    const float* Whh_f     = (const float*)d_in[4];
    const float* b_f       = (const float*)d_in[5];
    const float* Wih_b     = (const float*)d_in[6];
    const float* Whh_b     = (const float*)d_in[7];
    const float* b_b       = (const float*)d_in[8];
    const float* Ua        = (const float*)d_in[9];
    const float* Wa        = (const float*)d_in[10];
    const float* va        = (const float*)d_in[11];
    float* out = (float*)d_out;

    cudaFuncSetAttribute(recur_kernel, cudaFuncAttributeMaxDynamicSharedMemorySize, 98816);

    zerobar_kernel<<<1, 256>>>();
    pregemm_kernel<<<dim3(16, 128), 256>>>(concepts, lens, embedding,
                                           Wih_f, b_f, Wih_b, b_b);
    recur_kernel<<<128, 256, 98816>>>(Whh_f, Whh_b, lens);
    uw_kernel<<<256, 256>>>(Ua, Wa);
    scores_kernel<<<dim3(4, 64), 256>>>(va, out, (long)out_size);
}

// round 8
// speedup vs baseline: 1.2466x; 1.2466x over previous
#include <cuda_runtime.h>
#include <math.h>

#define S_LEN 128
#define BATCH 64
#define EMB   256
#define HID_H 256
#define NHID  30

typedef unsigned long long ull;

// ---------------- f32x2 helpers (FFMA2 only reachable via PTX) ----------------
__device__ __forceinline__ ull fma2(ull a, ull b, ull c) {
    ull d;
    asm("fma.rn.f32x2 %0, %1, %2, %3;" : "=l"(d) : "l"(a), "l"(b), "l"(c));
    return d;
}
__device__ __forceinline__ ull pack2(float lo, float hi) {
    ull d;
    asm("mov.b64 %0, {%1, %2};" : "=l"(d) : "f"(lo), "f"(hi));
    return d;
}
__device__ __forceinline__ void unpack2(ull v, float& lo, float& hi) {
    asm("mov.b64 {%0, %1}, %2;" : "=f"(lo), "=f"(hi) : "l"(v));
}

// ---------------- scratch (device globals; no allocation allowed) ----------------
__device__ float g_X[S_LEN * 2 * 1024 * BATCH];                 // 64 MB
__device__ float g_h[2 * 2 * 2 * 256 * 32];                     // 256 KB
__device__ float g_enc[BATCH * S_LEN * 512];                    // 16.8 MB
__device__ float g_uw[BATCH * S_LEN * 64];                      // 2 MB
__device__ int g_bar2[4 * 129];

// ---------------- barrier reset ----------------
__global__ void zerobar_kernel() {
    for (int i = threadIdx.x; i < 4 * 129; i += blockDim.x) g_bar2[i] = 0;
}

// ---------------- stage 1: pre-gates GEMM, f32x2, fused embedding gather ----------------
// grid (16 rowtiles, 128 t), block 256. Tile: 128 rows x 64 batches, k-block 16.
__global__ void __launch_bounds__(256) pregemm_kernel(
    const int* __restrict__ concepts, const int* __restrict__ lens,
    const float* __restrict__ embedding,
    const float* __restrict__ Wih_f, const float* __restrict__ b_f,
    const float* __restrict__ Wih_b, const float* __restrict__ b_b)
{
    __shared__ ull A2[16 * 130];
    __shared__ ull B2[16 * 34];
    __shared__ int tok_s[64];

    int t = blockIdx.y;
    int rowbase = blockIdx.x * 128;
    int dir = rowbase >> 10;
    int row0 = rowbase & 1023;
    const float* W    = dir ? Wih_b : Wih_f;
    const float* bias = dir ? b_b   : b_f;
    int tid = threadIdx.x;

    if (tid < 64) {
        int b = tid;
        int srow = t;
        if (dir) { int L = lens[b]; srow = (t < L) ? (L - 1 - t) : t; }
        tok_s[b] = concepts[srow * 64 + b];
    }
    __syncthreads();

    int tx = tid & 15, ty = tid >> 4;
    ull acc[8][2];
    #pragma unroll
    for (int i = 0; i < 8; i++) { acc[i][0] = 0ull; acc[i][1] = 0ull; }

    for (int k0 = 0; k0 < 256; k0 += 16) {
        #pragma unroll
        for (int i = 0; i < 2; i++) {
            int fidx = i * 256 + tid;
            int m = fidx >> 2, q = fidx & 3;
            float4 w4 = *(const float4*)&W[(row0 + m) * 256 + k0 + q * 4];
            A2[(q * 4 + 0) * 130 + m] = pack2(w4.x, w4.x);
            A2[(q * 4 + 1) * 130 + m] = pack2(w4.y, w4.y);
            A2[(q * 4 + 2) * 130 + m] = pack2(w4.z, w4.z);
            A2[(q * 4 + 3) * 130 + m] = pack2(w4.w, w4.w);
        }
        #pragma unroll
        for (int i = 0; i < 2; i++) {
            int fidx = i * 256 + tid;
            int bp = fidx >> 4, k = fidx & 15;
            float v0 = embedding[(long)tok_s[2 * bp]     * 256 + k0 + k];
            float v1 = embedding[(long)tok_s[2 * bp + 1] * 256 + k0 + k];
            B2[k * 34 + bp] = pack2(v0, v1);
        }
        __syncthreads();
        #pragma unroll
        for (int k = 0; k < 16; k++) {
            ulonglong2 bb = *(const ulonglong2*)&B2[k * 34 + tx * 2];
            #pragma unroll
            for (int u = 0; u < 4; u++) {
                ulonglong2 a = *(const ulonglong2*)&A2[k * 130 + ty * 8 + u * 2];
                acc[u * 2    ][0] = fma2(a.x, bb.x, acc[u * 2    ][0]);
                acc[u * 2    ][1] = fma2(a.x, bb.y, acc[u * 2    ][1]);
                acc[u * 2 + 1][0] = fma2(a.y, bb.x, acc[u * 2 + 1][0]);
                acc[u * 2 + 1][1] = fma2(a.y, bb.y, acc[u * 2 + 1][1]);
            }
        }
        __syncthreads();
    }

    #pragma unroll
    for (int i = 0; i < 8; i++) {
        int m = ty * 8 + i;
        float bv = bias[row0 + m];
        float x0, x1, x2, x3;
        unpack2(acc[i][0], x0, x1);
        unpack2(acc[i][1], x2, x3);
        float4 o = make_float4(x0 + bv, x1 + bv, x2 + bv, x3 + bv);
        *(float4*)&g_X[(((long)t * 2 + dir) * 1024 + row0 + m) * 64 + tx * 4] = o;
    }
}

// ---------------- stage 2: persistent LSTM recurrence (R4 scalar form) ----------------
// 128 CTAs: dir=cta>>6, bhalf=(cta&63)>>5, jgrp=cta&31 (8 hidden units).
// Whh slice (32 gate rows x 256) in smem; h double-buffered in global (L2),
// staged into smem each step; software barrier per (dir,bhalf) group of 32 CTAs.
__global__ void __launch_bounds__(256, 1) recur_kernel(
    const float* __restrict__ Whh_f, const float* __restrict__ Whh_b,
    const int* __restrict__ lens)
{
    extern __shared__ float sm[];        // [0,8192): w_s; [8192,16384): h_s (256 x 32)
    int cta = blockIdx.x;
    int dir   = cta >> 6;
    int bhalf = (cta & 63) >> 5;
    int jgrp  = cta & 31;
    int tid = threadIdx.x;
    int j = tid >> 5, lane = tid & 31;
    int hidx = jgrp * 8 + j;
    int bglob = bhalf * 32 + lane;
    int grp = dir * 2 + bhalf;
    const float* Whh = dir ? Whh_b : Whh_f;
    int L = lens[bglob];

    // load Whh slice: w_s[(g*8+j)*256 + k]
    {
        float4* w4 = (float4*)sm;
        #pragma unroll
        for (int i = 0; i < 8; i++) {
            int idx = i * 256 + tid;
            int r = idx >> 6, kq = idx & 63;
            int g = r >> 3, jj = r & 7;
            w4[r * 64 + kq] = *(const float4*)&Whh[((g * 256 + jgrp * 8 + jj) * 256 + kq * 4)];
        }
    }

    g_h[(((1 * 2 + dir) * 2 + bhalf) * 256 + hidx) * 32 + lane] = 0.f;
    __threadfence();
    __syncthreads();
    if (tid == 0) atomicAdd(&g_bar2[grp * 129 + 0], 1);

    float* h_s = sm + 8192;
    float c = 0.f;
    volatile int* barv = (volatile int*)g_bar2;

    for (int t = 0; t < S_LEN; t++) {
        // X loads before barrier (g_X is static after pregemm)
        long xb = ((long)t * 2 + dir) * 1024 * 64;
        float a0 = g_X[xb + (0   + hidx) * 64 + bglob];
        float a1 = g_X[xb + (256 + hidx) * 64 + bglob];
        float a2 = g_X[xb + (512 + hidx) * 64 + bglob];
        float a3 = g_X[xb + (768 + hidx) * 64 + bglob];

        if (tid == 0) {
            while (barv[grp * 129 + t] < 32) { __nanosleep(64); }
        }
        __syncthreads();
        __threadfence();

        // stage h_prev (parity (t+1)&1) into smem, L2-only loads
        {
            int rp = (t + 1) & 1;
            const float4* hp = (const float4*)&g_h[((rp * 2 + dir) * 2 + bhalf) * 8192];
            float4* hd = (float4*)h_s;
            #pragma unroll
            for (int i = 0; i < 8; i++) hd[i * 256 + tid] = __ldcg(hp + i * 256 + tid);
        }
        __syncthreads();

        #pragma unroll 4
        for (int k = 0; k < 256; k += 4) {
            float h0 = h_s[(k + 0) * 32 + lane];
            float h1 = h_s[(k + 1) * 32 + lane];
            float h2 = h_s[(k + 2) * 32 + lane];
            float h3 = h_s[(k + 3) * 32 + lane];
            float4 w0 = *(const float4*)&sm[(0 * 8 + j) * 256 + k];
            float4 w1 = *(const float4*)&sm[(1 * 8 + j) * 256 + k];
            float4 w2 = *(const float4*)&sm[(2 * 8 + j) * 256 + k];
            float4 w3 = *(const float4*)&sm[(3 * 8 + j) * 256 + k];
            a0 = fmaf(w0.x, h0, a0); a0 = fmaf(w0.y, h1, a0); a0 = fmaf(w0.z, h2, a0); a0 = fmaf(w0.w, h3, a0);
            a1 = fmaf(w1.x, h0, a1); a1 = fmaf(w1.y, h1, a1); a1 = fmaf(w1.z, h2, a1); a1 = fmaf(w1.w, h3, a1);
            a2 = fmaf(w2.x, h0, a2); a2 = fmaf(w2.y, h1, a2); a2 = fmaf(w2.z, h2, a2); a2 = fmaf(w2.w, h3, a2);
            a3 = fmaf(w3.x, h0, a3); a3 = fmaf(w3.y, h1, a3); a3 = fmaf(w3.z, h2, a3); a3 = fmaf(w3.w, h3, a3);
        }

        // fast activations (MUFU ex2 path): sigmoid and tanh via __expf
        float ei = __expf(-a0);
        float ef = __expf(-a1);
        float eg = __expf(-2.f * a2);
        float eo = __expf(-a3);
        float ig = __fdividef(1.f, 1.f + ei);
        float fg = __fdividef(1.f, 1.f + ef);
        float gg = __fdividef(2.f, 1.f + eg) - 1.f;
        float og = __fdividef(1.f, 1.f + eo);
        c = fg * c + ig * gg;
        float ec = __expf(-2.f * c);
        float hval = og * (__fdividef(2.f, 1.f + ec) - 1.f);

        // fused enc write (valid mask + backward un-reversal)
        bool valid = (t < L);
        float ev = valid ? hval : 0.f;
        if (dir == 0) {
            g_enc[((long)bglob * 128 + t) * 512 + hidx] = ev;
        } else {
            int tp = valid ? (L - 1 - t) : t;
            g_enc[((long)bglob * 128 + tp) * 512 + 256 + hidx] = ev;
        }

        if (t < S_LEN - 1) {
            int wp = t & 1;
            g_h[(((wp * 2 + dir) * 2 + bhalf) * 256 + hidx) * 32 + lane] = hval;
            __threadfence();
            __syncthreads();
            if (tid == 0) atomicAdd(&g_bar2[grp * 129 + t + 1], 1);
        }
    }
}

// ---------------- stage 3: u/w projections (enc[8192,512] @ W2[512,64]) ----------------
// grid 128 (pos tiles of 64), block 256, k-block 64 (8 iterations, 16 syncs total)
__global__ void __launch_bounds__(256) uw_kernel(
    const float* __restrict__ Ua, const float* __restrict__ Wa)
{
    __shared__ float A_s[64 * 72];   // [m][k], pad 72 for aligned float4
    __shared__ float B_s[64 * 72];   // [k][c], pad 72
    int pos0 = blockIdx.x * 64;
    int tid = threadIdx.x;
    int tx = tid & 15, ty = tid >> 4;

    float acc[4][4];
    #pragma unroll
    for (int i = 0; i < 4; i++) { acc[i][0]=0.f; acc[i][1]=0.f; acc[i][2]=0.f; acc[i][3]=0.f; }

    for (int k0 = 0; k0 < 512; k0 += 64) {
        // A fill: 64 m x 64 k = 1024 float4, 4 per thread
        #pragma unroll
        for (int i = 0; i < 4; i++) {
            int fidx = i * 256 + tid;
            int m = fidx >> 4, kq = fidx & 15;
            float4 v = *(const float4*)&g_enc[(long)(pos0 + m) * 512 + k0 + kq * 4];
            *(float4*)&A_s[m * 72 + kq * 4] = v;
        }
        // B fill: 64 c x 64 k, transposed scatter; 1024 float4 sources
        #pragma unroll
        for (int i = 0; i < 4; i++) {
            int fidx = i * 256 + tid;
            int cc = fidx >> 4, kq = fidx & 15;
            float4 v = make_float4(0.f, 0.f, 0.f, 0.f);
            if (cc < 30)      v = *(const float4*)&Ua[cc * 512 + k0 + kq * 4];
            else if (cc >= 32 && cc < 62) v = *(const float4*)&Wa[(cc - 32) * 512 + k0 + kq * 4];
            B_s[(kq * 4 + 0) * 72 + cc] = v.x;
            B_s[(kq * 4 + 1) * 72 + cc] = v.y;
            B_s[(kq * 4 + 2) * 72 + cc] = v.z;
            B_s[(kq * 4 + 3) * 72 + cc] = v.w;
        }
        __syncthreads();
        #pragma unroll 8
        for (int k = 0; k < 64; k++) {
            float4 b4 = *(const float4*)&B_s[k * 72 + tx * 4];
            #pragma unroll
            for (int i = 0; i < 4; i++) {
                float a = A_s[(ty * 4 + i) * 72 + k];
                acc[i][0] = fmaf(a, b4.x, acc[i][0]);
                acc[i][1] = fmaf(a, b4.y, acc[i][1]);
                acc[i][2] = fmaf(a, b4.z, acc[i][2]);
                acc[i][3] = fmaf(a, b4.w, acc[i][3]);
            }
        }
        __syncthreads();
    }
    #pragma unroll
    for (int i = 0; i < 4; i++) {
        *(float4*)&g_uw[(long)(pos0 + ty * 4 + i) * 64 + tx * 4] =
            make_float4(acc[i][0], acc[i][1], acc[i][2], acc[i][3]);
    }
}

// ---------------- stage 4: edge scores + predictions ----------------
__global__ void __launch_bounds__(256) scores_kernel(
    const float* __restrict__ va, float* __restrict__ out, long out_size)
{
    __shared__ float u_s[32 * 33];
    __shared__ float w_s[128 * 33];
    __shared__ float va_s[30];

    int b = blockIdx.y;
    int q0 = blockIdx.x * 32;
    int tid = threadIdx.x;

    for (int i = tid; i < 128 * 32; i += 256) {
        int k = i >> 5, h = i & 31;
        w_s[k * 33 + h] = g_uw[((long)b * 128 + k) * 64 + 32 + h];
    }
    for (int i = tid; i < 32 * 32; i += 256) {
        int q = i >> 5, h = i & 31;
        u_s[q * 33 + h] = g_uw[((long)b * 128 + q0 + q) * 64 + h];
    }
    if (tid < 30) va_s[tid] = va[tid];
    __syncthreads();

    int kk = tid & 127;
    int qoff = tid >> 7;
    bool preds = (out_size >= 2097152);
    #pragma unroll 1
    for (int i = 0; i < 16; i++) {
        int q = qoff * 16 + i;
        float s = 0.f;
        #pragma unroll
        for (int h = 0; h < 30; h++) {
            s = fmaf(va_s[h], tanhf(u_s[q * 33 + h] + w_s[kk * 33 + h]), s);
        }
        long oidx = ((long)b * 128 + q0 + q) * 128 + kk;
        out[oidx] = s;
        if (preds) out[1048576 + oidx] = (s >= 0.f) ? 1.f : 0.f;
    }
}

// ---------------- launch ----------------
extern "C" void kernel_launch(void* const* d_in, const int* in_sizes, int n_in,
                              void* d_out, int out_size) {
    const int*   concepts  = (const int*)  d_in[0];
    const int*   lens      = (const int*)  d_in[1];
    const float* embedding = (const float*)d_in[2];
    const float* Wih_f     = (const float*)d_in[3];
    const float* Whh_f     = (const float*)d_in[4];
    const float* b_f       = (const float*)d_in[5];
    const float* Wih_b     = (const float*)d_in[6];
    const float* Whh_b     = (const float*)d_in[7];
    const float* b_b       = (const float*)d_in[8];
    const float* Ua        = (const float*)d_in[9];
    const float* Wa        = (const float*)d_in[10];
    const float* va        = (const float*)d_in[11];
    float* out = (float*)d_out;

    cudaFuncSetAttribute(recur_kernel, cudaFuncAttributeMaxDynamicSharedMemorySize, 65536);

    zerobar_kernel<<<1, 256>>>();
    pregemm_kernel<<<dim3(16, 128), 256>>>(concepts, lens, embedding,
                                           Wih_f, b_f, Wih_b, b_b);
    recur_kernel<<<128, 256, 65536>>>(Whh_f, Whh_b, lens);
    uw_kernel<<<128, 256>>>(Ua, Wa);
    scores_kernel<<<dim3(4, 64), 256>>>(va, out, (long)out_size);
}